// round 8
// baseline (speedup 1.0000x reference)
#include <cuda_runtime.h>
#include <cuda_bf16.h>
#include <stdint.h>
#include <math.h>

#define BS 4096
#define AGENTS 128
#define OBSD 128
#define ACT 8
#define SD 4096
#define EMB 32
#define H1 128
#define H2 64

// ---------------- scratch (static device globals; no allocation) ----------------
__device__ float g_qs[(size_t)BS * AGENTS];           // agent_qs [b][a]
__device__ float g_act_fallback[(size_t)BS * AGENTS];
__device__ float g_C[(size_t)BS * SD];                // raw |states@Wh1 + bh1|  64MB
#define HKS 8
__device__ float g_hsp[(size_t)HKS * BS * 96];        // hyper_small partials [kz][b][96]

// bf16 split operands, plain row-major
__device__ __nv_bfloat16 g_Shi[(size_t)BS * SD];      // A hi  [m][k]
__device__ __nv_bfloat16 g_Slo[(size_t)BS * SD];      // A lo
__device__ __nv_bfloat16 g_Bhi[(size_t)SD * SD];      // B hi  [n][k]  (B[n][k] = Wh1[k][n])
__device__ __nv_bfloat16 g_Blo[(size_t)SD * SD];

// ============================ PTX helpers =====================================
__device__ __forceinline__ uint32_t smem_u32(const void* p) {
    uint32_t a;
    asm("{ .reg .u64 t; cvta.to.shared.u64 t, %1; cvt.u32.u64 %0, t; }" : "=r"(a) : "l"(p));
    return a;
}

__device__ __forceinline__ void cp16(uint32_t s, const void* g) {
    asm volatile("cp.async.cg.shared.global [%0], [%1], 16;" :: "r"(s), "l"(g));
}
#define CP_COMMIT() asm volatile("cp.async.commit_group;")
#define CP_WAIT1()  asm volatile("cp.async.wait_group 1;")

__device__ __forceinline__ void ldm4(uint32_t* r, uint32_t addr) {
    asm volatile("ldmatrix.sync.aligned.m8n8.x4.shared.b16 {%0,%1,%2,%3}, [%4];"
        : "=r"(r[0]), "=r"(r[1]), "=r"(r[2]), "=r"(r[3]) : "r"(addr));
}

__device__ __forceinline__ void mma_bf16(float* c, const uint32_t* a, const uint32_t* b) {
    asm volatile("mma.sync.aligned.m16n8k16.row.col.f32.bf16.bf16.f32 "
        "{%0,%1,%2,%3}, {%4,%5,%6,%7}, {%8,%9}, {%0,%1,%2,%3};"
        : "+f"(c[0]), "+f"(c[1]), "+f"(c[2]), "+f"(c[3])
        : "r"(a[0]), "r"(a[1]), "r"(a[2]), "r"(a[3]), "r"(b[0]), "r"(b[1]));
}

// =============================================================================
// Kernel 1: fused per-agent 3-layer MLP + max/argmax.
// BT=32 rows, 256 threads, 75KB smem (sized for co-residency with the GEMM).
// W1 staged in two 64-output-column halves.
// =============================================================================
#define MLP_BT 32
#define MLP_SMEM ((32*132 + 32*132 + 32*68 + 8192) * 4)   // 75,264 B

__global__ void __launch_bounds__(256) mlp_kernel(
    const float* __restrict__ obs,
    const float* __restrict__ W1, const float* __restrict__ b1,
    const float* __restrict__ W2, const float* __restrict__ b2,
    const float* __restrict__ W3, const float* __restrict__ b3,
    float* __restrict__ actions_out)
{
    extern __shared__ float sm[];
    float* obss = sm;                 // [32][132]
    float* x1s  = sm + 32*132;        // [32][132]
    float* x2s  = sm + 2*32*132;      // [32][68]
    float* ws   = sm + 2*32*132 + 32*68;   // 8192 floats (32KB)
    __shared__ float b1s[H1];
    __shared__ float b2s[H2];
    __shared__ float b3s[ACT];

    const int a   = blockIdx.x;
    const int b0  = blockIdx.y * MLP_BT;
    const int tid = threadIdx.x;

    if (tid < H1) b1s[tid] = b1[a*H1 + tid];
    if (tid < H2) b2s[tid] = b2[a*H2 + tid];
    if (tid < ACT) b3s[tid] = b3[a*ACT + tid];

    // stage obs tile [32][128] -> padded 132
    for (int i = tid; i < MLP_BT * (OBSD/4); i += 256) {
        int r  = i >> 5;
        int c4 = i & 31;
        float4 v = ((const float4*)(obs + ((size_t)(b0 + r) * AGENTS + a) * OBSD))[c4];
        *(float4*)(obss + r*132 + c4*4) = v;
    }

    // ---- layer 1 in two output-column halves ----
    #pragma unroll
    for (int h = 0; h < 2; h++) {
        // stage W1[:, h*64 : h*64+64]  (128 k-rows x 16 float4)
        for (int i = tid; i < 2048; i += 256) {
            int k = i >> 4, c4 = i & 15;
            *(float4*)(ws + k*64 + c4*4) =
                *(const float4*)(W1 + (size_t)a * OBSD * H1 + (size_t)k * H1 + h*64 + c4*4);
        }
        __syncthreads();

        const int ty = tid >> 4, tx = tid & 15;   // rows ty*2.., cols tx*4 within half
        float acc[2][4];
        #pragma unroll
        for (int i = 0; i < 2; i++)
            #pragma unroll
            for (int j = 0; j < 4; j++) acc[i][j] = 0.f;

        #pragma unroll 4
        for (int k = 0; k < OBSD; k++) {
            float a0 = obss[(ty*2+0)*132 + k];
            float a1 = obss[(ty*2+1)*132 + k];
            float4 w = *(const float4*)(ws + k*64 + tx*4);
            float wv[4] = {w.x, w.y, w.z, w.w};
            #pragma unroll
            for (int j = 0; j < 4; j++) {
                acc[0][j] = fmaf(a0, wv[j], acc[0][j]);
                acc[1][j] = fmaf(a1, wv[j], acc[1][j]);
            }
        }
        #pragma unroll
        for (int i = 0; i < 2; i++) {
            float4 o;
            float* ov = (float*)&o;
            #pragma unroll
            for (int j = 0; j < 4; j++) {
                float v = acc[i][j] + b1s[h*64 + tx*4 + j];
                ov[j] = v > 0.f ? v : 0.f;
            }
            *(float4*)(x1s + (ty*2+i)*132 + h*64 + tx*4) = o;
        }
        __syncthreads();   // ws reused next half / next layer
    }

    // ---- layer 2: stage W2 [128][64] fully ----
    for (int i = tid; i < 2048; i += 256) {
        ((float4*)ws)[i] = ((const float4*)(W2 + (size_t)a * H1 * H2))[i];
    }
    __syncthreads();

    {
        const int row = tid >> 3, tx = tid & 7;   // one row, 8 cols each
        float acc[8];
        #pragma unroll
        for (int j = 0; j < 8; j++) acc[j] = 0.f;
        #pragma unroll 4
        for (int k = 0; k < H1; k++) {
            float x = x1s[row*132 + k];
            float4 w0 = *(const float4*)(ws + k*H2 + tx*8);
            float4 w1v = *(const float4*)(ws + k*H2 + tx*8 + 4);
            acc[0] = fmaf(x, w0.x, acc[0]);
            acc[1] = fmaf(x, w0.y, acc[1]);
            acc[2] = fmaf(x, w0.z, acc[2]);
            acc[3] = fmaf(x, w0.w, acc[3]);
            acc[4] = fmaf(x, w1v.x, acc[4]);
            acc[5] = fmaf(x, w1v.y, acc[5]);
            acc[6] = fmaf(x, w1v.z, acc[6]);
            acc[7] = fmaf(x, w1v.w, acc[7]);
        }
        float4 o0, o1;
        float* ov0 = (float*)&o0; float* ov1 = (float*)&o1;
        #pragma unroll
        for (int j = 0; j < 4; j++) {
            float v = acc[j] + b2s[tx*8 + j];
            ov0[j] = v > 0.f ? v : 0.f;
            float v2 = acc[4+j] + b2s[tx*8 + 4 + j];
            ov1[j] = v2 > 0.f ? v2 : 0.f;
        }
        *(float4*)(x2s + row*68 + tx*8)     = o0;
        *(float4*)(x2s + row*68 + tx*8 + 4) = o1;
    }
    __syncthreads();

    // ---- layer 3: stage W3 [64][8] ----
    if (tid < 128) ((float4*)ws)[tid] = ((const float4*)(W3 + (size_t)a * H2 * ACT))[tid];
    __syncthreads();

    if (tid < MLP_BT) {
        const int r = tid;
        float acc[8];
        #pragma unroll
        for (int c = 0; c < 8; c++) acc[c] = 0.f;
        #pragma unroll 4
        for (int k = 0; k < H2; k++) {
            float x = x2s[r*68 + k];
            float4 w0  = *(const float4*)(ws + k*ACT);
            float4 w1v = *(const float4*)(ws + k*ACT + 4);
            acc[0] = fmaf(x, w0.x, acc[0]);
            acc[1] = fmaf(x, w0.y, acc[1]);
            acc[2] = fmaf(x, w0.z, acc[2]);
            acc[3] = fmaf(x, w0.w, acc[3]);
            acc[4] = fmaf(x, w1v.x, acc[4]);
            acc[5] = fmaf(x, w1v.y, acc[5]);
            acc[6] = fmaf(x, w1v.z, acc[6]);
            acc[7] = fmaf(x, w1v.w, acc[7]);
        }
        float best = acc[0] + b3s[0];
        int bi = 0;
        #pragma unroll
        for (int c = 1; c < 8; c++) {
            float q = acc[c] + b3s[c];
            if (q > best) { best = q; bi = c; }
        }
        g_qs[(size_t)(b0 + r) * AGENTS + a]        = best;
        actions_out[(size_t)(b0 + r) * AGENTS + a] = (float)bi;
    }
}

// =============================================================================
// Conversion: states -> hi/lo bf16 row-major (elementwise, coalesced)
// =============================================================================
__global__ void __launch_bounds__(256) conv_S_kernel(const float* __restrict__ S)
{
    const size_t id = (size_t)blockIdx.x * 256 + threadIdx.x;   // one per 8 elems
    const float4* src = (const float4*)(S + id * 8);
    float4 v0 = src[0], v1 = src[1];
    float x[8] = {v0.x, v0.y, v0.z, v0.w, v1.x, v1.y, v1.z, v1.w};
    uint32_t hw[4], lw[4];
    #pragma unroll
    for (int p = 0; p < 4; p++) {
        __nv_bfloat16 h0 = __float2bfloat16(x[p*2]);
        __nv_bfloat16 h1 = __float2bfloat16(x[p*2+1]);
        __nv_bfloat16 l0 = __float2bfloat16(x[p*2]   - __bfloat162float(h0));
        __nv_bfloat16 l1 = __float2bfloat16(x[p*2+1] - __bfloat162float(h1));
        hw[p] = (uint32_t)__bfloat16_as_ushort(h0) | ((uint32_t)__bfloat16_as_ushort(h1) << 16);
        lw[p] = (uint32_t)__bfloat16_as_ushort(l0) | ((uint32_t)__bfloat16_as_ushort(l1) << 16);
    }
    ((uint4*)g_Shi)[id] = make_uint4(hw[0], hw[1], hw[2], hw[3]);
    ((uint4*)g_Slo)[id] = make_uint4(lw[0], lw[1], lw[2], lw[3]);
}

// =============================================================================
// Conversion + transpose: Wh1[k][n] -> B[n][k] hi/lo bf16 (64x64 smem tiles)
// =============================================================================
__global__ void __launch_bounds__(256) conv_W_kernel(const float* __restrict__ Wh1)
{
    __shared__ float tile[64][65];
    const int kt = blockIdx.x & 63;
    const int nt = blockIdx.x >> 6;
    const int tid = threadIdx.x;

    #pragma unroll
    for (int p = 0; p < 16; p++) {
        int idx = p * 256 + tid;
        int r = idx >> 6, c = idx & 63;      // r = k, c = n
        tile[r][c] = Wh1[(size_t)(kt*64 + r) * SD + nt*64 + c];
    }
    __syncthreads();

    #pragma unroll
    for (int p = 0; p < 2; p++) {
        int id = p * 256 + tid;
        int n = id >> 3, kc = id & 7;
        uint32_t hw[4], lw[4];
        #pragma unroll
        for (int q = 0; q < 4; q++) {
            float x0 = tile[kc*8 + q*2][n];
            float x1 = tile[kc*8 + q*2 + 1][n];
            __nv_bfloat16 h0 = __float2bfloat16(x0);
            __nv_bfloat16 h1 = __float2bfloat16(x1);
            __nv_bfloat16 l0 = __float2bfloat16(x0 - __bfloat162float(h0));
            __nv_bfloat16 l1 = __float2bfloat16(x1 - __bfloat162float(h1));
            hw[q] = (uint32_t)__bfloat16_as_ushort(h0) | ((uint32_t)__bfloat16_as_ushort(h1) << 16);
            lw[q] = (uint32_t)__bfloat16_as_ushort(l0) | ((uint32_t)__bfloat16_as_ushort(l1) << 16);
        }
        size_t off = ((size_t)(nt*64 + n) * SD + kt*64 + kc*8) / 8;
        ((uint4*)g_Bhi)[off] = make_uint4(hw[0], hw[1], hw[2], hw[3]);
        ((uint4*)g_Blo)[off] = make_uint4(lw[0], lw[1], lw[2], lw[3]);
    }
}

// =============================================================================
// mma.sync bf16 3-split GEMM. 128x128 CTA tile, BK=32, 3-stage cp.async
// (120KB smem -> co-resident with mlp_kernel). Epilogue writes RAW
// |acc + bh1| to g_C (no qs dependency -> GEMM runs concurrently with MLP).
// =============================================================================
#define GSTAGES 3
#define OP_BYTES 10240
#define STAGE_BYTES (4 * OP_BYTES)
#define GEMM_SMEM (GSTAGES * STAGE_BYTES)
#define NKT (SD / 32)

__global__ void __launch_bounds__(256) hyper_gemm_mma(const float* __restrict__ bh1)
{
    extern __shared__ char gsm[];
    __shared__ float sbias[128];

    const int tid = threadIdx.x;
    const int wid = tid >> 5, lane = tid & 31;
    const int warpM = wid & 3, warpN = wid >> 2;
    const int bx = blockIdx.x >> 5;    // N tile
    const int by = blockIdx.x & 31;    // M tile

    const uint32_t sbase = smem_u32(gsm);

    if (tid < 128) sbias[tid] = bh1[bx*128 + tid];

    const char* Ahi_g = (const char*)(g_Shi + (size_t)(by*128) * SD);
    const char* Alo_g = (const char*)(g_Slo + (size_t)(by*128) * SD);
    const char* Bhi_g = (const char*)(g_Bhi + (size_t)(bx*128) * SD);
    const char* Blo_g = (const char*)(g_Blo + (size_t)(bx*128) * SD);

    const int id0 = tid, id1 = tid + 256;
    const int m0 = id0 >> 2, c0 = id0 & 3;
    const int m1 = id1 >> 2, c1 = id1 & 3;
    const uint32_t s_off0 = (uint32_t)(m0*5 + c0) * 16;
    const uint32_t s_off1 = (uint32_t)(m1*5 + c1) * 16;

    #define ISSUE_STAGE(stg, kt_) do { \
        const uint32_t sb_ = sbase + (stg) * STAGE_BYTES; \
        const size_t g0_ = ((size_t)m0 * SD + (size_t)(kt_)*32 + c0*8) * 2; \
        const size_t g1_ = ((size_t)m1 * SD + (size_t)(kt_)*32 + c1*8) * 2; \
        cp16(sb_ + 0*OP_BYTES + s_off0, Ahi_g + g0_); \
        cp16(sb_ + 0*OP_BYTES + s_off1, Ahi_g + g1_); \
        cp16(sb_ + 1*OP_BYTES + s_off0, Alo_g + g0_); \
        cp16(sb_ + 1*OP_BYTES + s_off1, Alo_g + g1_); \
        cp16(sb_ + 2*OP_BYTES + s_off0, Bhi_g + g0_); \
        cp16(sb_ + 2*OP_BYTES + s_off1, Bhi_g + g1_); \
        cp16(sb_ + 3*OP_BYTES + s_off0, Blo_g + g0_); \
        cp16(sb_ + 3*OP_BYTES + s_off1, Blo_g + g1_); \
        CP_COMMIT(); \
    } while (0)

    uint32_t offA[2][2], offB[4][2];
    {
        const int am = warpM*32 + (lane & 7) + ((lane >> 3) & 1) * 8;
        #pragma unroll
        for (int mt = 0; mt < 2; mt++)
            #pragma unroll
            for (int ks = 0; ks < 2; ks++)
                offA[mt][ks] = (uint32_t)((am + mt*16)*5 + ks*2 + (lane >> 4)) * 16;
        const int bn = warpN*64 + (lane & 7) + ((lane >> 4) & 1) * 8;
        #pragma unroll
        for (int ntp = 0; ntp < 4; ntp++)
            #pragma unroll
            for (int ks = 0; ks < 2; ks++)
                offB[ntp][ks] = (uint32_t)((bn + ntp*16)*5 + ks*2 + ((lane >> 3) & 1)) * 16;
    }

    float acc[2][8][4];
    #pragma unroll
    for (int mt = 0; mt < 2; mt++)
        #pragma unroll
        for (int nt = 0; nt < 8; nt++)
            #pragma unroll
            for (int q = 0; q < 4; q++) acc[mt][nt][q] = 0.f;

    // prologue: 2 stages ahead
    ISSUE_STAGE(0, 0);
    ISSUE_STAGE(1, 1);

    for (int kt = 0; kt < NKT; kt++) {
        CP_WAIT1();
        __syncthreads();

        if (kt + 2 < NKT) ISSUE_STAGE((kt + 2) % GSTAGES, kt + 2);

        const uint32_t stg = sbase + (kt % GSTAGES) * STAGE_BYTES;
        const uint32_t aHi = stg + 0*OP_BYTES, aLo = stg + 1*OP_BYTES;
        const uint32_t bHi = stg + 2*OP_BYTES, bLo = stg + 3*OP_BYTES;

        #pragma unroll
        for (int ks = 0; ks < 2; ks++) {
            uint32_t ah[2][4], al[2][4], bh[8][2], bl[8][2];
            #pragma unroll
            for (int mt = 0; mt < 2; mt++) {
                ldm4(ah[mt], aHi + offA[mt][ks]);
                ldm4(al[mt], aLo + offA[mt][ks]);
            }
            #pragma unroll
            for (int ntp = 0; ntp < 4; ntp++) {
                uint32_t r[4];
                ldm4(r, bHi + offB[ntp][ks]);
                bh[2*ntp][0] = r[0]; bh[2*ntp][1] = r[1];
                bh[2*ntp+1][0] = r[2]; bh[2*ntp+1][1] = r[3];
                ldm4(r, bLo + offB[ntp][ks]);
                bl[2*ntp][0] = r[0]; bl[2*ntp][1] = r[1];
                bl[2*ntp+1][0] = r[2]; bl[2*ntp+1][1] = r[3];
            }
            #pragma unroll
            for (int mt = 0; mt < 2; mt++)
                #pragma unroll
                for (int nt = 0; nt < 8; nt++) {
                    mma_bf16(acc[mt][nt], ah[mt], bh[nt]);
                    mma_bf16(acc[mt][nt], al[mt], bh[nt]);
                    mma_bf16(acc[mt][nt], ah[mt], bl[nt]);
                }
        }
        __syncthreads();
    }

    // --------- epilogue: write raw |acc + bias| ---------
    #pragma unroll
    for (int mt = 0; mt < 2; mt++) {
        #pragma unroll
        for (int rr = 0; rr < 2; rr++) {
            const int row = by*128 + warpM*32 + mt*16 + (lane >> 2) + rr*8;
            float* dst = g_C + (size_t)row * SD + bx*128;
            #pragma unroll
            for (int nt = 0; nt < 8; nt++) {
                const int col = warpN*64 + nt*8 + (lane & 3)*2;
                float v0 = fabsf(acc[mt][nt][rr*2 + 0] + sbias[col]);
                float v1 = fabsf(acc[mt][nt][rr*2 + 1] + sbias[col + 1]);
                *(float2*)(dst + col) = make_float2(v0, v1);
            }
        }
    }
}

// =============================================================================
// Skinny hypernet GEMMs, K-split by HKS. (unchanged from R7)
// =============================================================================
__global__ void __launch_bounds__(256) hyper_small_kernel(
    const float* __restrict__ S,
    const float* __restrict__ Whb,
    const float* __restrict__ Whf,
    const float* __restrict__ Wv1)
{
    __shared__ __align__(16) float ss[64][36];
    __shared__ __align__(16) float wbs[64][32];
    __shared__ __align__(16) float wfs[64][32];
    __shared__ __align__(16) float wvs[64][32];

    const int b0  = blockIdx.x * 32;
    const int kz  = blockIdx.y;
    const int kbeg = kz * (SD / HKS);
    const int tid = threadIdx.x;
    const int e   = tid & 31;
    const int rg  = tid >> 5;

    float ab[4] = {0,0,0,0}, af[4] = {0,0,0,0}, av[4] = {0,0,0,0};

    for (int kc = 0; kc < SD/HKS; kc += 64) {
        const int k0 = kbeg + kc;
        __syncthreads();
        for (int i = tid; i < 512; i += 256) {
            int r = i >> 4, c4 = (i & 15) * 4;
            float4 v = *(const float4*)(S + (size_t)(b0 + r) * SD + k0 + c4);
            ss[c4+0][r] = v.x; ss[c4+1][r] = v.y; ss[c4+2][r] = v.z; ss[c4+3][r] = v.w;
        }
        for (int i = tid; i < 512; i += 256) {
            int kk = i >> 3, c = (i & 7) * 4;
            *(float4*)&wbs[kk][c] = *(const float4*)(Whb + (size_t)(k0+kk)*EMB + c);
            *(float4*)&wfs[kk][c] = *(const float4*)(Whf + (size_t)(k0+kk)*EMB + c);
            *(float4*)&wvs[kk][c] = *(const float4*)(Wv1 + (size_t)(k0+kk)*EMB + c);
        }
        __syncthreads();
        #pragma unroll 4
        for (int k = 0; k < 64; k++) {
            float wb = wbs[k][e], wf = wfs[k][e], wv = wvs[k][e];
            #pragma unroll
            for (int i = 0; i < 4; i++) {
                float s = ss[k][rg*4 + i];
                ab[i] = fmaf(s, wb, ab[i]);
                af[i] = fmaf(s, wf, af[i]);
                av[i] = fmaf(s, wv, av[i]);
            }
        }
    }
    #pragma unroll
    for (int i = 0; i < 4; i++) {
        int b = b0 + rg*4 + i;
        float* dst = g_hsp + ((size_t)kz * BS + b) * 96;
        dst[e]      = ab[i];
        dst[32 + e] = af[i];
        dst[64 + e] = av[i];
    }
}

// =============================================================================
// Final mixing: qs-fold over raw C (128 agents), hyper_small K-slice reduce,
// elu, dot with w_final + V. One block per batch row.
// =============================================================================
__global__ void __launch_bounds__(128) final_kernel(
    const float* __restrict__ bhb, const float* __restrict__ bhf,
    const float* __restrict__ bv1,
    const float* __restrict__ Wv2, const float* __restrict__ bv2,
    float* __restrict__ qtot)
{
    __shared__ float red[128];
    const int b = blockIdx.x;
    const int t = threadIdx.x;
    const float* Crow = g_C + (size_t)b * SD;
    const float* qrow = g_qs + (size_t)b * AGENTS;

    float s = 0.f;
    const int abase = t >> 5;
    #pragma unroll 8
    for (int j = 0; j < 32; j++)
        s = fmaf(qrow[abase + 4*j], Crow[t + 128*j], s);
    red[t] = s;
    __syncthreads();

    if (t < 32) {
        const int e = t;
        float hp = red[e] + red[e+32] + red[e+64] + red[e+96];

        float sb = 0.f, wf = 0.f, rv = 0.f;
        #pragma unroll
        for (int kz = 0; kz < HKS; kz++) {
            const float* src = g_hsp + ((size_t)kz * BS + b) * 96;
            sb += src[e];
            wf += src[32 + e];
            rv += src[64 + e];
        }
        sb += bhb[e];
        wf = fabsf(wf + bhf[e]);
        rv += bv1[e];
        rv = rv > 0.f ? rv : 0.f;

        hp += sb;
        float hidden = hp > 0.f ? hp : expm1f(hp);
        float contrib = hidden * wf + rv * Wv2[e];
        #pragma unroll
        for (int o = 16; o > 0; o >>= 1)
            contrib += __shfl_down_sync(0xffffffffu, contrib, o);
        if (e == 0) qtot[b] = contrib + bv2[0];
    }
}

// =============================================================================
extern "C" void kernel_launch(void* const* d_in, const int* in_sizes, int n_in,
                              void* d_out, int out_size)
{
    const float* obs    = (const float*)d_in[0];
    const float* states = (const float*)d_in[1];
    const float* W1  = (const float*)d_in[2];
    const float* b1  = (const float*)d_in[3];
    const float* W2  = (const float*)d_in[4];
    const float* b2  = (const float*)d_in[5];
    const float* W3  = (const float*)d_in[6];
    const float* b3  = (const float*)d_in[7];
    const float* Wh1 = (const float*)d_in[8];
    const float* bh1 = (const float*)d_in[9];
    const float* Whb = (const float*)d_in[10];
    const float* bhb = (const float*)d_in[11];
    const float* Whf = (const float*)d_in[12];
    const float* bhf = (const float*)d_in[13];
    const float* Wv1 = (const float*)d_in[14];
    const float* bv1 = (const float*)d_in[15];
    const float* Wv2 = (const float*)d_in[16];
    const float* bv2 = (const float*)d_in[17];
    float* out = (float*)d_out;

    cudaFuncSetAttribute(mlp_kernel, cudaFuncAttributeMaxDynamicSharedMemorySize, MLP_SMEM);
    cudaFuncSetAttribute(hyper_gemm_mma, cudaFuncAttributeMaxDynamicSharedMemorySize, GEMM_SMEM);

    float* act_dst;
    if (out_size >= (int)(BS + BS*AGENTS)) {
        act_dst = out + BS;
    } else {
        void* p = 0;
        cudaGetSymbolAddress(&p, g_act_fallback);
        act_dst = (float*)p;
    }

    // One-time creation of side stream + fork/join events (outside capture:
    // the first harness call is the correctness run; capture reuses handles).
    static cudaStream_t sB = 0;
    static cudaEvent_t evFork = 0, evJoin = 0;
    if (sB == 0) {
        cudaStreamCreateWithFlags(&sB, cudaStreamNonBlocking);
        cudaEventCreateWithFlags(&evFork, cudaEventDisableTiming);
        cudaEventCreateWithFlags(&evJoin, cudaEventDisableTiming);
    }

    if (sB != 0) {
        // fork: stream B runs FFMA-heavy work concurrently with the GEMM
        cudaEventRecord(evFork, 0);
        cudaStreamWaitEvent(sB, evFork, 0);

        mlp_kernel<<<dim3(AGENTS, BS/MLP_BT), 256, MLP_SMEM, sB>>>(
            obs, W1, b1, W2, b2, W3, b3, act_dst);
        hyper_small_kernel<<<dim3(BS/32, HKS), 256, 0, sB>>>(states, Whb, Whf, Wv1);
        cudaEventRecord(evJoin, sB);

        // origin stream: conversions then tensor-pipe GEMM (no qs dependency)
        conv_S_kernel<<<BS*SD/8/256, 256>>>(states);
        conv_W_kernel<<<4096, 256>>>(Wh1);
        hyper_gemm_mma<<<1024, 256, GEMM_SMEM>>>(bh1);

        // join, then final mixing
        cudaStreamWaitEvent(0, evJoin, 0);
        final_kernel<<<BS, 128>>>(bhb, bhf, bv1, Wv2, bv2, out);
    } else {
        // fallback: fully sequential on the default stream
        mlp_kernel<<<dim3(AGENTS, BS/MLP_BT), 256, MLP_SMEM>>>(
            obs, W1, b1, W2, b2, W3, b3, act_dst);
        hyper_small_kernel<<<dim3(BS/32, HKS), 256>>>(states, Whb, Whf, Wv1);
        conv_S_kernel<<<BS*SD/8/256, 256>>>(states);
        conv_W_kernel<<<4096, 256>>>(Wh1);
        hyper_gemm_mma<<<1024, 256, GEMM_SMEM>>>(bh1);
        final_kernel<<<BS, 128>>>(bhb, bhf, bv1, Wv2, bv2, out);
    }
}